// round 13
// baseline (speedup 1.0000x reference)
#include <cuda_runtime.h>
#include <cstdint>

#define BB 64
#define TT 512
#define DD 256
#define UU 512
#define NCTA 128

// ---------------- fallback (R10) config ----------------
#define NTH 288
#define WROW 520
#define REDO 52
#define H_BYTES  (64 * 2048)
#define W_OFF    H_BYTES
#define W_BYTES  (3 * 4 * WROW * 4)
#define R_OFF    (W_OFF + W_BYTES)
#define R_BYTES  (256 * REDO * 4)
#define FLAG_OFF (R_OFF + R_BYTES)
#define SM_TOTAL (FLAG_OFF + 16)

// ---------------- cluster config ----------------
#define CL 16
#define CW_BYTES (3 * 32 * 512 * 4)          // 196608 weights (96 rows x 2048B)
#define CH_OFF   CW_BYTES
#define CH_BYTES (8 * 512 * 4)               // 16384: full h, 8 rows, linear
#define CR_OFF   (CH_OFF + CH_BYTES)         // 212992
#define CR_BYTES (768 * 4)                   // 3072
#define CSM_TOTAL (CR_OFF + CR_BYTES)        // 216064

// Scratch (static device arrays; no cudaMalloc anywhere).
__device__ float g_xp[3][TT][BB][UU];
__device__ float g_hbuf[2][BB * UU];
__device__ unsigned g_count;

__device__ __forceinline__ void fma2(unsigned long long &d, unsigned long long a,
                                     unsigned long long b) {
    asm("fma.rn.f32x2 %0, %1, %2, %0;" : "+l"(d) : "l"(a), "l"(b));
}
__device__ __forceinline__ float2 upk(unsigned long long v) {
    float2 r;
    asm("mov.b64 {%0, %1}, %2;" : "=f"(r.x), "=f"(r.y) : "l"(v));
    return r;
}
__device__ __forceinline__ void cp16(uint32_t dst, const float* src) {
    asm volatile("cp.async.cg.shared.global [%0], [%1], 16;" :: "r"(dst), "l"(src));
}
__device__ __forceinline__ float fsig(float x) {
    return __fdividef(1.0f, 1.0f + __expf(-x));
}
__device__ __forceinline__ float ftanh(float x) {
    float e = __expf(-2.0f * fabsf(x));
    float r = __fdividef(1.0f - e, 1.0f + e);
    return copysignf(r, x);
}

// ============================================================================
// Phase 1: xp[g][t][b][u] = x[b,t,:] @ w_xg[:,u] + b_g[u]   (unchanged)
// ============================================================================
__global__ void __launch_bounds__(256, 2) proj_kernel(
    const float* __restrict__ x,
    const float* __restrict__ wxi, const float* __restrict__ wxf,
    const float* __restrict__ wxc,
    const float* __restrict__ bi, const float* __restrict__ bf,
    const float* __restrict__ bc) {
    __shared__ __align__(16) float xs[64][33];
    __shared__ __align__(16) float ws[3][32][64];

    const int tid = threadIdx.x;
    const int t = blockIdx.y;
    const int ub = blockIdx.x * 64;

    const int ug = tid & 15;
    const int bg = tid >> 4;
    const int ul = ug << 2;
    const int b0 = bg << 2;

    unsigned long long acc[3][4][2];
#pragma unroll
    for (int g = 0; g < 3; ++g)
#pragma unroll
        for (int i = 0; i < 4; ++i) { acc[g][i][0] = 0ull; acc[g][i][1] = 0ull; }

    for (int k0 = 0; k0 < DD; k0 += 32) {
#pragma unroll
        for (int i = 0; i < 8; ++i) {
            int idx = tid + i * 256;
            int bb = idx >> 5, kk = idx & 31;
            xs[bb][kk] = x[(bb * TT + t) * DD + k0 + kk];
        }
#pragma unroll
        for (int i = 0; i < 24; ++i) {
            int idx = tid + i * 256;
            int g = idx >> 11, r = idx & 2047, kk = r >> 6, uu = r & 63;
            const float* w = (g == 0) ? wxi : ((g == 1) ? wxf : wxc);
            ws[g][kk][uu] = w[(k0 + kk) * UU + ub + uu];
        }
        __syncthreads();
#pragma unroll
        for (int kk = 0; kk < 32; ++kk) {
            unsigned long long xb[4];
#pragma unroll
            for (int i = 0; i < 4; ++i) {
                unsigned xv = __float_as_uint(xs[b0 + i][kk]);
                asm("mov.b64 %0, {%1, %1};" : "=l"(xb[i]) : "r"(xv));
            }
#pragma unroll
            for (int g = 0; g < 3; ++g) {
                const ulonglong2 wv = *(const ulonglong2*)&ws[g][kk][ul];
#pragma unroll
                for (int i = 0; i < 4; ++i) {
                    fma2(acc[g][i][0], xb[i], wv.x);
                    fma2(acc[g][i][1], xb[i], wv.y);
                }
            }
        }
        __syncthreads();
    }

    const float* biases[3] = {bi, bf, bc};
#pragma unroll
    for (int g = 0; g < 3; ++g) {
        float2 bv0 = *(const float2*)&biases[g][ub + ul];
        float2 bv1 = *(const float2*)&biases[g][ub + ul + 2];
#pragma unroll
        for (int i = 0; i < 4; ++i) {
            float2 r0 = upk(acc[g][i][0]);
            float2 r1 = upk(acc[g][i][1]);
            r0.x += bv0.x; r0.y += bv0.y;
            r1.x += bv1.x; r1.y += bv1.y;
            float* dst = &g_xp[g][t][b0 + i][ub + ul];
            *(float2*)dst = r0;
            *(float2*)(dst + 2) = r1;
        }
    }
}

__global__ void init_kernel(const float* __restrict__ h0) {
    int i = blockIdx.x * blockDim.x + threadIdx.x;
    if (i < BB * UU) g_hbuf[1][i] = h0[i];
    if (i == 0) g_count = 0u;
}

// ============================================================================
// CLUSTER kernel: 8 independent clusters x 16 CTAs; cluster owns 8 batch rows
// for all T; rank owns 32 u-cols x 3 gates, weights smem-resident.
// Full h (8 rows x 512, linear) replicated in every CTA's smem.
// Thread (ks=tid&15, cg=tid>>4): cols cg*2,cg*2+1 (x3 gates), 8 rows,
// k-groups kg=j*16+ks, j=0..7.  8 h-LDS + 6 w-LDS per j for 96 fma2.
// ks-reduce: 4x shfl_xor (1,2,4,8); lanes (lane&15)==0 write sred[768].
// Gates: thread (b2=tid>>5, c2=tid&31). h exchange: 16x st.shared::cluster
// (mapa). Split cluster barriers: A = reads done, B = writes published.
// ============================================================================
__global__ void __launch_bounds__(256, 1)
lstm_cluster(const float* __restrict__ whi, const float* __restrict__ whf,
             const float* __restrict__ whc, const float* __restrict__ h0,
             const float* __restrict__ c0, float* __restrict__ out) {
    extern __shared__ __align__(16) char sm[];
    float* sred = (float*)(sm + CR_OFF);

    const int tid = threadIdx.x;
    const int lane = tid & 31;
    const int ks = tid & 15;
    const int cg = tid >> 4;                 // 0..15 -> cols cg*2, cg*2+1
    const int b2 = tid >> 5, c2 = tid & 31;  // gate roles
    uint32_t rank;
    asm("mov.u32 %0, %%cluster_ctarank;" : "=r"(rank));
    const int cid = blockIdx.x >> 4;
    const int u0 = (int)rank * 32;
    const int gb = cid * 8 + b2;

    // weights -> smem: row (g*32+c)*2048, slot (k>>2)^(c&7), inner k&3
    for (int i = tid; i < 3 * 32 * 512; i += 256) {
        int cc = i & 31, k = (i >> 5) & 511, g = i >> 14;
        const float* wsrc = (g == 0) ? whi : ((g == 1) ? whf : whc);
        float v = wsrc[k * UU + u0 + cc];
        *(float*)(sm + (g * 32 + cc) * 2048 +
                  (((k >> 2) ^ (cc & 7)) << 4) + (k & 3) * 4) = v;
    }
    // h0 -> local full-h (linear)
    for (int i = tid; i < 8 * 512; i += 256) {
        int b = i >> 9, uu = i & 511;
        *(float*)(sm + CH_OFF + b * 2048 + uu * 4) = h0[(cid * 8 + b) * UU + uu];
    }
    float cst = c0[gb * UU + u0 + c2];
    __syncthreads();

    // DSMEM destinations for this thread's h element (row b2, col u0+c2)
    const uint32_t smbase = (uint32_t)__cvta_generic_to_shared(sm);
    uint32_t dst[CL];
    {
        uint32_t lofs = smbase + CH_OFF + (uint32_t)(b2 * 2048 + (u0 + c2) * 4);
#pragma unroll
        for (int p = 0; p < CL; ++p)
            asm("mapa.shared::cluster.u32 %0, %1, %2;"
                : "=r"(dst[p]) : "r"(lofs), "r"(p));
    }

    // compute-phase base pointers
    const char* hb = sm + CH_OFF + (ks << 4);          // + b*2048 + j*256
    const char* wp[3][2];
#pragma unroll
    for (int g = 0; g < 3; ++g)
#pragma unroll
        for (int q = 0; q < 2; ++q) {
            int cc = cg * 2 + q;
            wp[g][q] = sm + (g * 32 + cc) * 2048 + ((ks ^ (cc & 7)) << 4);
        }

    const size_t gstride = (size_t)TT * BB * UU;
    const float* xpi = &g_xp[0][0][0][0] + 0 * gstride + (size_t)gb * UU + u0 + c2;
    const float* xpf = &g_xp[0][0][0][0] + 1 * gstride + (size_t)gb * UU + u0 + c2;
    const float* xpc = &g_xp[0][0][0][0] + 2 * gstride + (size_t)gb * UU + u0 + c2;
    float* orow = out + (size_t)gb * TT * UU + u0 + c2;

    float pi = __ldcg(xpi), pf = __ldcg(xpf), pc = __ldcg(xpc);

    for (int t = 0; t < TT; ++t) {
        unsigned long long acc[8][3][2];
#pragma unroll
        for (int b = 0; b < 8; ++b)
#pragma unroll
            for (int g = 0; g < 3; ++g) { acc[b][g][0] = 0ull; acc[b][g][1] = 0ull; }

#pragma unroll
        for (int j = 0; j < 8; ++j) {
            ulonglong2 wv[3][2];
#pragma unroll
            for (int g = 0; g < 3; ++g)
#pragma unroll
                for (int q = 0; q < 2; ++q)
                    wv[g][q] = *(const ulonglong2*)(wp[g][q] + j * 256);
#pragma unroll
            for (int b = 0; b < 8; ++b) {
                const ulonglong2 hv =
                    *(const ulonglong2*)(hb + b * 2048 + j * 256);
#pragma unroll
                for (int g = 0; g < 3; ++g)
#pragma unroll
                    for (int q = 0; q < 2; ++q) {
                        fma2(acc[b][g][q], hv.x, wv[g][q].x);
                        fma2(acc[b][g][q], hv.y, wv[g][q].y);
                    }
            }
        }
        // local h reads done
        if (t < TT - 1)
            asm volatile("barrier.cluster.arrive.aligned;" ::: "memory"); // A

        // ks-reduce via shfl (bits 0..3 of lane)
        float s[8][3][2];
#pragma unroll
        for (int b = 0; b < 8; ++b)
#pragma unroll
            for (int g = 0; g < 3; ++g)
#pragma unroll
                for (int q = 0; q < 2; ++q) {
                    float2 v = upk(acc[b][g][q]);
                    float sv = v.x + v.y;
                    sv += __shfl_xor_sync(0xffffffffu, sv, 1);
                    sv += __shfl_xor_sync(0xffffffffu, sv, 2);
                    sv += __shfl_xor_sync(0xffffffffu, sv, 4);
                    sv += __shfl_xor_sync(0xffffffffu, sv, 8);
                    s[b][g][q] = sv;
                }
        if ((lane & 15) == 0) {
#pragma unroll
            for (int b = 0; b < 8; ++b)
#pragma unroll
                for (int g = 0; g < 3; ++g)
#pragma unroll
                    for (int q = 0; q < 2; ++q)
                        sred[(b * 3 + g) * 32 + cg * 2 + q] = s[b][g][q];
        }
        __syncthreads();

        float S0 = sred[(b2 * 3 + 0) * 32 + c2];
        float S1 = sred[(b2 * 3 + 1) * 32 + c2];
        float S2 = sred[(b2 * 3 + 2) * 32 + c2];
        float ig = fsig(pi + S0);
        float fg = fsig(pf + S1);
        float cin = ftanh(pc + S2);
        cst = fg * cst + ig * cin;
        float hn = ftanh(cst);
        orow[(size_t)t * UU] = hn;

        if (t < TT - 1) {
            asm volatile("barrier.cluster.wait.aligned;" ::: "memory");   // A
#pragma unroll
            for (int p = 0; p < CL; ++p)
                asm volatile("st.shared::cluster.f32 [%0], %1;"
                             :: "r"(dst[p]), "f"(hn) : "memory");
            asm volatile("barrier.cluster.arrive.aligned;" ::: "memory"); // B
            pi = __ldcg(xpi + (size_t)(t + 1) * (BB * UU));
            pf = __ldcg(xpf + (size_t)(t + 1) * (BB * UU));
            pc = __ldcg(xpc + (size_t)(t + 1) * (BB * UU));
            asm volatile("barrier.cluster.wait.aligned;" ::: "memory");   // B
        }
    }
    // clean DSMEM teardown
    asm volatile("barrier.cluster.arrive.aligned;" ::: "memory");
    asm volatile("barrier.cluster.wait.aligned;" ::: "memory");
}

// ============================================================================
// FALLBACK: R10 persistent kernel (proven ~3075 us), verbatim.
// ============================================================================
__global__ void __launch_bounds__(NTH, 1) lstm_fallback(
    const float* __restrict__ whi, const float* __restrict__ whf,
    const float* __restrict__ whc, const float* __restrict__ c0,
    float* __restrict__ out) {
    extern __shared__ __align__(16) char sm[];
    float* smW = (float*)(sm + W_OFF);
    float* smR = (float*)(sm + R_OFF);

    const int tid = threadIdx.x;
    const int wid = tid >> 5, lane = tid & 31;
    const int u0 = blockIdx.x * 4;
    const int c  = tid & 1;
    const int bg = (tid >> 1) & 7;
    const int ks = tid >> 4;
    const int rot = (ks & 1) * 2;
    const int lr = lane >> 3, ls = lane & 7;
    const int b2 = tid >> 2, c2 = tid & 3;
    const int u = u0 + c2;

    {
        const float* wsrc[3] = {whi, whf, whc};
        for (int i = tid; i < 3 * 4 * UU; i += NTH) {
            int cc = i & 3, k = (i >> 2) & 511, g = i >> 11;
            smW[(g * 4 + cc) * WROW + k] = wsrc[g][k * UU + u0 + cc];
        }
    }
    float cst = (tid < 256) ? c0[b2 * UU + u] : 0.0f;

    const uint32_t smbase = (uint32_t)__cvta_generic_to_shared(sm);
    const uint32_t flagaddr = smbase + FLAG_OFF;
    if (tid == 0) *(unsigned*)(sm + FLAG_OFF) = 0u;

    const int perm = bg * 2 + c;
    float* redw = smR + (bg * 8) * 4 * REDO + (c * 2) * REDO + (ks ^ perm);
    const float* redr = smR + tid * REDO;

    const size_t gstride = (size_t)TT * BB * UU;
    const float* xpi = &g_xp[0][0][0][0] + 0 * gstride + (size_t)b2 * UU + u;
    const float* xpf = &g_xp[0][0][0][0] + 1 * gstride + (size_t)b2 * UU + u;
    const float* xpc = &g_xp[0][0][0][0] + 2 * gstride + (size_t)b2 * UU + u;
    float* orow = out + (size_t)b2 * TT * UU + u;

    __syncthreads();

    for (int t = 0; t < TT; ++t) {
        if (tid < 256) {
            float pi = __ldcg(xpi + (size_t)t * (BB * UU));
            float pf = __ldcg(xpf + (size_t)t * (BB * UU));
            float pc = __ldcg(xpc + (size_t)t * (BB * UU));

            if (t > 0) {
                unsigned v;
                do {
                    asm volatile("ld.acquire.cta.shared.u32 %0, [%1];"
                                 : "=r"(v) : "r"(flagaddr) : "memory");
                } while (v < (unsigned)t);
            }

            const float* hsrc = &g_hbuf[(t + 1) & 1][0];
#pragma unroll
            for (int j = 0; j < 32; ++j) {
                int jr = j & 15, js = j >> 4;
                int r = jr * 4 + lr;
                int s = wid * 16 + js * 8 + ls;
                uint32_t dst = smbase + r * 2048 +
                               (uint32_t)((s ^ ((r >> 3) & 7)) << 4);
                cp16(dst, hsrc + r * 512 + s * 4);
            }
            asm volatile("cp.async.commit_group;");
            asm volatile("cp.async.wait_group 0;");
            __syncwarp();

            unsigned long long acc[8][3][2];
#pragma unroll
            for (int i = 0; i < 8; ++i)
#pragma unroll
                for (int g = 0; g < 3; ++g) {
                    acc[i][g][0] = 0ull; acc[i][g][1] = 0ull;
                }

#pragma unroll
            for (int j = 0; j < 8; ++j) {
                const int k4 = ks * 8 + ((j + rot) & 7);
                ulonglong2 wv[3][2];
#pragma unroll
                for (int g = 0; g < 3; ++g)
#pragma unroll
                    for (int q = 0; q < 2; ++q)
                        wv[g][q] = *(const ulonglong2*)(
                            smW + (g * 4 + c * 2 + q) * WROW + k4 * 4);
                const uint32_t koff = (uint32_t)((k4 ^ bg) << 4);
                const char* hbb = sm + (bg * 8) * 2048 + koff;
#pragma unroll
                for (int i = 0; i < 8; ++i) {
                    const ulonglong2 hv = *(const ulonglong2*)(hbb + i * 2048);
#pragma unroll
                    for (int g = 0; g < 3; ++g)
#pragma unroll
                        for (int q = 0; q < 2; ++q) {
                            fma2(acc[i][g][q], hv.x, wv[g][q].x);
                            fma2(acc[i][g][q], hv.y, wv[g][q].y);
                        }
                }
            }

#pragma unroll
            for (int i = 0; i < 8; ++i)
#pragma unroll
                for (int g = 0; g < 3; ++g)
#pragma unroll
                    for (int q = 0; q < 2; ++q) {
                        float2 v = upk(acc[i][g][q]);
                        redw[i * 4 * REDO + q * REDO + g * 16] = v.x + v.y;
                    }
            __syncthreads();

            float s[3];
#pragma unroll
            for (int g = 0; g < 3; ++g) {
                const float* rb = redr + g * 16;
                float4 a = *(const float4*)(rb + 0);
                float4 b = *(const float4*)(rb + 4);
                float4 d = *(const float4*)(rb + 8);
                float4 e = *(const float4*)(rb + 12);
                s[g] = (((a.x + a.y) + (a.z + a.w)) + ((b.x + b.y) + (b.z + b.w)))
                     + (((d.x + d.y) + (d.z + d.w)) + ((e.x + e.y) + (e.z + e.w)));
            }
            float ig = fsig(pi + s[0]);
            float fg = fsig(pf + s[1]);
            float cin = ftanh(pc + s[2]);
            cst = fg * cst + ig * cin;
            float hn = ftanh(cst);
            __stcg(&g_hbuf[t & 1][b2 * UU + u], hn);
            orow[(size_t)t * UU] = hn;

            if (t < TT - 1) {
                asm volatile("membar.cta;" ::: "memory");
                asm volatile("bar.arrive 1, %0;" :: "n"(NTH) : "memory");
            }
        } else {
            __syncthreads();
            if (t < TT - 1) {
                asm volatile("bar.sync 1, %0;" :: "n"(NTH) : "memory");
                if (lane == 0) {
                    asm volatile("red.release.gpu.global.add.u32 [%0], 1;"
                                 :: "l"(&g_count) : "memory");
                    unsigned target = (unsigned)(t + 1) * NCTA;
                    unsigned v;
                    do {
                        asm volatile("ld.acquire.gpu.u32 %0, [%1];"
                                     : "=r"(v) : "l"(&g_count) : "memory");
                    } while (v < target);
                    asm volatile("st.release.cta.shared.u32 [%0], %1;"
                                 :: "r"(flagaddr), "r"((unsigned)(t + 1))
                                 : "memory");
                }
                __syncwarp();
            }
        }
    }
}

extern "C" void kernel_launch(void* const* d_in, const int* in_sizes, int n_in,
                              void* d_out, int out_size) {
    const float* x   = (const float*)d_in[0];
    const float* wxi = (const float*)d_in[1];
    const float* wxf = (const float*)d_in[2];
    const float* wxc = (const float*)d_in[3];
    const float* whi = (const float*)d_in[4];
    const float* whf = (const float*)d_in[5];
    const float* whc = (const float*)d_in[6];
    const float* bi  = (const float*)d_in[7];
    const float* bf  = (const float*)d_in[8];
    const float* bc  = (const float*)d_in[9];
    const float* h0  = (const float*)d_in[10];
    const float* c0  = (const float*)d_in[11];
    float* out = (float*)d_out;

    proj_kernel<<<dim3(8, TT), 256>>>(x, wxi, wxf, wxc, bi, bf, bc);
    init_kernel<<<(BB * UU + 255) / 256, 256>>>(h0);

    bool launched = false;
    cudaError_t e1 = cudaFuncSetAttribute(
        lstm_cluster, cudaFuncAttributeNonPortableClusterSizeAllowed, 1);
    cudaError_t e2 = cudaFuncSetAttribute(
        lstm_cluster, cudaFuncAttributeMaxDynamicSharedMemorySize, CSM_TOTAL);
    if (e1 == cudaSuccess && e2 == cudaSuccess) {
        cudaLaunchConfig_t cfg = {};
        cfg.gridDim = dim3(NCTA, 1, 1);
        cfg.blockDim = dim3(256, 1, 1);
        cfg.dynamicSmemBytes = CSM_TOTAL;
        cudaLaunchAttribute at[1];
        at[0].id = cudaLaunchAttributeClusterDimension;
        at[0].val.clusterDim.x = CL;
        at[0].val.clusterDim.y = 1;
        at[0].val.clusterDim.z = 1;
        cfg.attrs = at;
        cfg.numAttrs = 1;
        cudaError_t e3 = cudaLaunchKernelEx(&cfg, lstm_cluster,
                                            whi, whf, whc, h0, c0, out);
        if (e3 == cudaSuccess) launched = true;
        else (void)cudaGetLastError();
    } else {
        (void)cudaGetLastError();
    }
    if (!launched) {
        cudaFuncSetAttribute(lstm_fallback,
                             cudaFuncAttributeMaxDynamicSharedMemorySize,
                             SM_TOTAL);
        lstm_fallback<<<NCTA, NTH, SM_TOTAL>>>(whi, whf, whc, c0, out);
    }
}

// round 14
// speedup vs baseline: 1.0507x; 1.0507x over previous
#include <cuda_runtime.h>
#include <cstdint>

#define BB 64
#define TT 512
#define DD 256
#define UU 512
#define NCTA 128

// ---------------- fallback (R10) config ----------------
#define NTH 288
#define WROW 520
#define REDO 52
#define H_BYTES  (64 * 2048)
#define W_OFF    H_BYTES
#define W_BYTES  (3 * 4 * WROW * 4)
#define R_OFF    (W_OFF + W_BYTES)
#define R_BYTES  (256 * REDO * 4)
#define FLAG_OFF (R_OFF + R_BYTES)
#define SM_TOTAL (FLAG_OFF + 16)

// ---------------- cluster config ----------------
#define CL 16
#define CW_BYTES (3 * 32 * 512 * 4)          // 196608 weights (96 rows x 2048B)
#define CH_OFF   CW_BYTES
#define CH_BYTES (8 * 512 * 4)               // 16384: full h, 8 rows, linear
#define CR_OFF   (CH_OFF + CH_BYTES)         // 212992
#define CR_BYTES (768 * 4)                   // 3072
#define CSM_TOTAL (CR_OFF + CR_BYTES)        // 216064

// Scratch (static device arrays; no cudaMalloc anywhere).
__device__ float g_xp[3][TT][BB][UU];
__device__ float g_hbuf[2][BB * UU];
__device__ float g_hcl[2][8][8][512];        // ping-pong per-cluster h slices
__device__ unsigned g_count;

__device__ __forceinline__ void fma2(unsigned long long &d, unsigned long long a,
                                     unsigned long long b) {
    asm("fma.rn.f32x2 %0, %1, %2, %0;" : "+l"(d) : "l"(a), "l"(b));
}
__device__ __forceinline__ float2 upk(unsigned long long v) {
    float2 r;
    asm("mov.b64 {%0, %1}, %2;" : "=f"(r.x), "=f"(r.y) : "l"(v));
    return r;
}
__device__ __forceinline__ void cp16(uint32_t dst, const float* src) {
    asm volatile("cp.async.cg.shared.global [%0], [%1], 16;" :: "r"(dst), "l"(src));
}
__device__ __forceinline__ float fsig(float x) {
    return __fdividef(1.0f, 1.0f + __expf(-x));
}
__device__ __forceinline__ float ftanh(float x) {
    float e = __expf(-2.0f * fabsf(x));
    float r = __fdividef(1.0f - e, 1.0f + e);
    return copysignf(r, x);
}

// ============================================================================
// Phase 1: xp[g][t][b][u] = x[b,t,:] @ w_xg[:,u] + b_g[u]   (unchanged)
// ============================================================================
__global__ void __launch_bounds__(256, 2) proj_kernel(
    const float* __restrict__ x,
    const float* __restrict__ wxi, const float* __restrict__ wxf,
    const float* __restrict__ wxc,
    const float* __restrict__ bi, const float* __restrict__ bf,
    const float* __restrict__ bc) {
    __shared__ __align__(16) float xs[64][33];
    __shared__ __align__(16) float ws[3][32][64];

    const int tid = threadIdx.x;
    const int t = blockIdx.y;
    const int ub = blockIdx.x * 64;

    const int ug = tid & 15;
    const int bg = tid >> 4;
    const int ul = ug << 2;
    const int b0 = bg << 2;

    unsigned long long acc[3][4][2];
#pragma unroll
    for (int g = 0; g < 3; ++g)
#pragma unroll
        for (int i = 0; i < 4; ++i) { acc[g][i][0] = 0ull; acc[g][i][1] = 0ull; }

    for (int k0 = 0; k0 < DD; k0 += 32) {
#pragma unroll
        for (int i = 0; i < 8; ++i) {
            int idx = tid + i * 256;
            int bb = idx >> 5, kk = idx & 31;
            xs[bb][kk] = x[(bb * TT + t) * DD + k0 + kk];
        }
#pragma unroll
        for (int i = 0; i < 24; ++i) {
            int idx = tid + i * 256;
            int g = idx >> 11, r = idx & 2047, kk = r >> 6, uu = r & 63;
            const float* w = (g == 0) ? wxi : ((g == 1) ? wxf : wxc);
            ws[g][kk][uu] = w[(k0 + kk) * UU + ub + uu];
        }
        __syncthreads();
#pragma unroll
        for (int kk = 0; kk < 32; ++kk) {
            unsigned long long xb[4];
#pragma unroll
            for (int i = 0; i < 4; ++i) {
                unsigned xv = __float_as_uint(xs[b0 + i][kk]);
                asm("mov.b64 %0, {%1, %1};" : "=l"(xb[i]) : "r"(xv));
            }
#pragma unroll
            for (int g = 0; g < 3; ++g) {
                const ulonglong2 wv = *(const ulonglong2*)&ws[g][kk][ul];
#pragma unroll
                for (int i = 0; i < 4; ++i) {
                    fma2(acc[g][i][0], xb[i], wv.x);
                    fma2(acc[g][i][1], xb[i], wv.y);
                }
            }
        }
        __syncthreads();
    }

    const float* biases[3] = {bi, bf, bc};
#pragma unroll
    for (int g = 0; g < 3; ++g) {
        float2 bv0 = *(const float2*)&biases[g][ub + ul];
        float2 bv1 = *(const float2*)&biases[g][ub + ul + 2];
#pragma unroll
        for (int i = 0; i < 4; ++i) {
            float2 r0 = upk(acc[g][i][0]);
            float2 r1 = upk(acc[g][i][1]);
            r0.x += bv0.x; r0.y += bv0.y;
            r1.x += bv1.x; r1.y += bv1.y;
            float* dst = &g_xp[g][t][b0 + i][ub + ul];
            *(float2*)dst = r0;
            *(float2*)(dst + 2) = r1;
        }
    }
}

__global__ void init_kernel(const float* __restrict__ h0) {
    int i = blockIdx.x * blockDim.x + threadIdx.x;
    if (i < BB * UU) g_hbuf[1][i] = h0[i];
    if (i == 0) g_count = 0u;
}

// ============================================================================
// CLUSTER kernel: 8 independent clusters x 16 CTAs; cluster owns 8 batch rows
// for all T; rank owns 32 u-cols x 3 gates, weights smem-resident.
// h exchange through L2: each CTA stcg's its 1KB slice into a ping-pong gmem
// buffer, ONE cluster barrier (arrive=release / wait=acquire, cluster scope),
// then cp.asyncs the full 16KB slice into smem. No cross-CTA smem access.
// Compute: thread (ks=tid&15, cg=tid>>4): cols cg*2,cg*2+1 x 3 gates, 8 rows.
// ks-reduce via 4x shfl_xor; gates: thread (b2=tid>>5, c2=tid&31).
// ============================================================================
__global__ void __launch_bounds__(256, 1)
lstm_cluster(const float* __restrict__ whi, const float* __restrict__ whf,
             const float* __restrict__ whc, const float* __restrict__ h0,
             const float* __restrict__ c0, float* __restrict__ out) {
    extern __shared__ __align__(16) char sm[];
    float* sred = (float*)(sm + CR_OFF);

    const int tid = threadIdx.x;
    const int lane = tid & 31;
    const int ks = tid & 15;
    const int cg = tid >> 4;                 // 0..15 -> cols cg*2, cg*2+1
    const int b2 = tid >> 5, c2 = tid & 31;  // gate roles
    uint32_t rank;
    asm("mov.u32 %0, %%cluster_ctarank;" : "=r"(rank));
    const int cid = blockIdx.x >> 4;
    const int u0 = (int)rank * 32;
    const int gb = cid * 8 + b2;

    // weights -> smem: row (g*32+c)*2048, slot (k>>2)^(c&7), inner k&3
    for (int i = tid; i < 3 * 32 * 512; i += 256) {
        int cc = i & 31, k = (i >> 5) & 511, g = i >> 14;
        const float* wsrc = (g == 0) ? whi : ((g == 1) ? whf : whc);
        float v = wsrc[k * UU + u0 + cc];
        *(float*)(sm + (g * 32 + cc) * 2048 +
                  (((k >> 2) ^ (cc & 7)) << 4) + (k & 3) * 4) = v;
    }
    const uint32_t smbase = (uint32_t)__cvta_generic_to_shared(sm);
    // h0 -> smem (linear, 16KB via cp.async)
    {
        const float* src = h0 + (size_t)cid * 8 * UU;
#pragma unroll
        for (int k = 0; k < 4; ++k) {
            int idx = tid + k * 256;                 // 16B chunk index, 0..1023
            cp16(smbase + CH_OFF + (uint32_t)(idx << 4), src + idx * 4);
        }
        asm volatile("cp.async.commit_group;");
    }
    float cst = c0[gb * UU + u0 + c2];
    asm volatile("cp.async.wait_group 0;");
    __syncthreads();

    // compute-phase base pointers
    const char* hb = sm + CH_OFF + (ks << 4);          // + b*2048 + j*256
    const char* wp[3][2];
#pragma unroll
    for (int g = 0; g < 3; ++g)
#pragma unroll
        for (int q = 0; q < 2; ++q) {
            int cc = cg * 2 + q;
            wp[g][q] = sm + (g * 32 + cc) * 2048 + ((ks ^ (cc & 7)) << 4);
        }

    const size_t gstride = (size_t)TT * BB * UU;
    const float* xpi = &g_xp[0][0][0][0] + 0 * gstride + (size_t)gb * UU + u0 + c2;
    const float* xpf = &g_xp[0][0][0][0] + 1 * gstride + (size_t)gb * UU + u0 + c2;
    const float* xpc = &g_xp[0][0][0][0] + 2 * gstride + (size_t)gb * UU + u0 + c2;
    float* orow = out + (size_t)gb * TT * UU + u0 + c2;
    // exchange buffer addresses for this thread
    float* sl_w = &g_hcl[0][cid][b2][u0 + c2];         // + (t&1)*8*8*512
    const float* sl_r = &g_hcl[0][cid][0][0];

    float pi = __ldcg(xpi), pf = __ldcg(xpf), pc = __ldcg(xpc);

    for (int t = 0; t < TT; ++t) {
        unsigned long long acc[8][3][2];
#pragma unroll
        for (int b = 0; b < 8; ++b)
#pragma unroll
            for (int g = 0; g < 3; ++g) { acc[b][g][0] = 0ull; acc[b][g][1] = 0ull; }

#pragma unroll
        for (int j = 0; j < 8; ++j) {
            ulonglong2 wv[3][2];
#pragma unroll
            for (int g = 0; g < 3; ++g)
#pragma unroll
                for (int q = 0; q < 2; ++q)
                    wv[g][q] = *(const ulonglong2*)(wp[g][q] + j * 256);
#pragma unroll
            for (int b = 0; b < 8; ++b) {
                const ulonglong2 hv =
                    *(const ulonglong2*)(hb + b * 2048 + j * 256);
#pragma unroll
                for (int g = 0; g < 3; ++g)
#pragma unroll
                    for (int q = 0; q < 2; ++q) {
                        fma2(acc[b][g][q], hv.x, wv[g][q].x);
                        fma2(acc[b][g][q], hv.y, wv[g][q].y);
                    }
            }
        }

        // ks-reduce via shfl (bits 0..3 of lane)
        float s[8][3][2];
#pragma unroll
        for (int b = 0; b < 8; ++b)
#pragma unroll
            for (int g = 0; g < 3; ++g)
#pragma unroll
                for (int q = 0; q < 2; ++q) {
                    float2 v = upk(acc[b][g][q]);
                    float sv = v.x + v.y;
                    sv += __shfl_xor_sync(0xffffffffu, sv, 1);
                    sv += __shfl_xor_sync(0xffffffffu, sv, 2);
                    sv += __shfl_xor_sync(0xffffffffu, sv, 4);
                    sv += __shfl_xor_sync(0xffffffffu, sv, 8);
                    s[b][g][q] = sv;
                }
        if ((lane & 15) == 0) {
#pragma unroll
            for (int b = 0; b < 8; ++b)
#pragma unroll
                for (int g = 0; g < 3; ++g)
#pragma unroll
                    for (int q = 0; q < 2; ++q)
                        sred[(b * 3 + g) * 32 + cg * 2 + q] = s[b][g][q];
        }
        __syncthreads();

        float S0 = sred[(b2 * 3 + 0) * 32 + c2];
        float S1 = sred[(b2 * 3 + 1) * 32 + c2];
        float S2 = sred[(b2 * 3 + 2) * 32 + c2];
        float ig = fsig(pi + S0);
        float fg = fsig(pf + S1);
        float cin = ftanh(pc + S2);
        cst = fg * cst + ig * cin;
        float hn = ftanh(cst);
        orow[(size_t)t * UU] = hn;

        if (t < TT - 1) {
            const int buf = t & 1;
            // publish own 1KB slice (coalesced)
            __stcg(sl_w + buf * (8 * 8 * 512), hn);
            // one cluster barrier: release stores / acquire before reads
            asm volatile("barrier.cluster.arrive.aligned;" ::: "memory");
            pi = __ldcg(xpi + (size_t)(t + 1) * (BB * UU));
            pf = __ldcg(xpf + (size_t)(t + 1) * (BB * UU));
            pc = __ldcg(xpc + (size_t)(t + 1) * (BB * UU));
            asm volatile("barrier.cluster.wait.aligned;" ::: "memory");
            // stage full 16KB slice -> smem
            const float* src = sl_r + buf * (8 * 8 * 512);
#pragma unroll
            for (int k = 0; k < 4; ++k) {
                int idx = tid + k * 256;
                cp16(smbase + CH_OFF + (uint32_t)(idx << 4), src + idx * 4);
            }
            asm volatile("cp.async.commit_group;");
            asm volatile("cp.async.wait_group 0;");
            __syncthreads();
        }
    }
}

// ============================================================================
// FALLBACK: R10 persistent kernel (proven ~3075 us), verbatim.
// ============================================================================
__global__ void __launch_bounds__(NTH, 1) lstm_fallback(
    const float* __restrict__ whi, const float* __restrict__ whf,
    const float* __restrict__ whc, const float* __restrict__ c0,
    float* __restrict__ out) {
    extern __shared__ __align__(16) char sm[];
    float* smW = (float*)(sm + W_OFF);
    float* smR = (float*)(sm + R_OFF);

    const int tid = threadIdx.x;
    const int wid = tid >> 5, lane = tid & 31;
    const int u0 = blockIdx.x * 4;
    const int c  = tid & 1;
    const int bg = (tid >> 1) & 7;
    const int ks = tid >> 4;
    const int rot = (ks & 1) * 2;
    const int lr = lane >> 3, ls = lane & 7;
    const int b2 = tid >> 2, c2 = tid & 3;
    const int u = u0 + c2;

    {
        const float* wsrc[3] = {whi, whf, whc};
        for (int i = tid; i < 3 * 4 * UU; i += NTH) {
            int cc = i & 3, k = (i >> 2) & 511, g = i >> 11;
            smW[(g * 4 + cc) * WROW + k] = wsrc[g][k * UU + u0 + cc];
        }
    }
    float cst = (tid < 256) ? c0[b2 * UU + u] : 0.0f;

    const uint32_t smbase = (uint32_t)__cvta_generic_to_shared(sm);
    const uint32_t flagaddr = smbase + FLAG_OFF;
    if (tid == 0) *(unsigned*)(sm + FLAG_OFF) = 0u;

    const int perm = bg * 2 + c;
    float* redw = smR + (bg * 8) * 4 * REDO + (c * 2) * REDO + (ks ^ perm);
    const float* redr = smR + tid * REDO;

    const size_t gstride = (size_t)TT * BB * UU;
    const float* xpi = &g_xp[0][0][0][0] + 0 * gstride + (size_t)b2 * UU + u;
    const float* xpf = &g_xp[0][0][0][0] + 1 * gstride + (size_t)b2 * UU + u;
    const float* xpc = &g_xp[0][0][0][0] + 2 * gstride + (size_t)b2 * UU + u;
    float* orow = out + (size_t)b2 * TT * UU + u;

    __syncthreads();

    for (int t = 0; t < TT; ++t) {
        if (tid < 256) {
            float pi = __ldcg(xpi + (size_t)t * (BB * UU));
            float pf = __ldcg(xpf + (size_t)t * (BB * UU));
            float pc = __ldcg(xpc + (size_t)t * (BB * UU));

            if (t > 0) {
                unsigned v;
                do {
                    asm volatile("ld.acquire.cta.shared.u32 %0, [%1];"
                                 : "=r"(v) : "r"(flagaddr) : "memory");
                } while (v < (unsigned)t);
            }

            const float* hsrc = &g_hbuf[(t + 1) & 1][0];
#pragma unroll
            for (int j = 0; j < 32; ++j) {
                int jr = j & 15, js = j >> 4;
                int r = jr * 4 + lr;
                int s = wid * 16 + js * 8 + ls;
                uint32_t dst = smbase + r * 2048 +
                               (uint32_t)((s ^ ((r >> 3) & 7)) << 4);
                cp16(dst, hsrc + r * 512 + s * 4);
            }
            asm volatile("cp.async.commit_group;");
            asm volatile("cp.async.wait_group 0;");
            __syncwarp();

            unsigned long long acc[8][3][2];
#pragma unroll
            for (int i = 0; i < 8; ++i)
#pragma unroll
                for (int g = 0; g < 3; ++g) {
                    acc[i][g][0] = 0ull; acc[i][g][1] = 0ull;
                }

#pragma unroll
            for (int j = 0; j < 8; ++j) {
                const int k4 = ks * 8 + ((j + rot) & 7);
                ulonglong2 wv[3][2];
#pragma unroll
                for (int g = 0; g < 3; ++g)
#pragma unroll
                    for (int q = 0; q < 2; ++q)
                        wv[g][q] = *(const ulonglong2*)(
                            smW + (g * 4 + c * 2 + q) * WROW + k4 * 4);
                const uint32_t koff = (uint32_t)((k4 ^ bg) << 4);
                const char* hbb = sm + (bg * 8) * 2048 + koff;
#pragma unroll
                for (int i = 0; i < 8; ++i) {
                    const ulonglong2 hv = *(const ulonglong2*)(hbb + i * 2048);
#pragma unroll
                    for (int g = 0; g < 3; ++g)
#pragma unroll
                        for (int q = 0; q < 2; ++q) {
                            fma2(acc[i][g][q], hv.x, wv[g][q].x);
                            fma2(acc[i][g][q], hv.y, wv[g][q].y);
                        }
                }
            }

#pragma unroll
            for (int i = 0; i < 8; ++i)
#pragma unroll
                for (int g = 0; g < 3; ++g)
#pragma unroll
                    for (int q = 0; q < 2; ++q) {
                        float2 v = upk(acc[i][g][q]);
                        redw[i * 4 * REDO + q * REDO + g * 16] = v.x + v.y;
                    }
            __syncthreads();

            float s[3];
#pragma unroll
            for (int g = 0; g < 3; ++g) {
                const float* rb = redr + g * 16;
                float4 a = *(const float4*)(rb + 0);
                float4 b = *(const float4*)(rb + 4);
                float4 d = *(const float4*)(rb + 8);
                float4 e = *(const float4*)(rb + 12);
                s[g] = (((a.x + a.y) + (a.z + a.w)) + ((b.x + b.y) + (b.z + b.w)))
                     + (((d.x + d.y) + (d.z + d.w)) + ((e.x + e.y) + (e.z + e.w)));
            }
            float ig = fsig(pi + s[0]);
            float fg = fsig(pf + s[1]);
            float cin = ftanh(pc + s[2]);
            cst = fg * cst + ig * cin;
            float hn = ftanh(cst);
            __stcg(&g_hbuf[t & 1][b2 * UU + u], hn);
            orow[(size_t)t * UU] = hn;

            if (t < TT - 1) {
                asm volatile("membar.cta;" ::: "memory");
                asm volatile("bar.arrive 1, %0;" :: "n"(NTH) : "memory");
            }
        } else {
            __syncthreads();
            if (t < TT - 1) {
                asm volatile("bar.sync 1, %0;" :: "n"(NTH) : "memory");
                if (lane == 0) {
                    asm volatile("red.release.gpu.global.add.u32 [%0], 1;"
                                 :: "l"(&g_count) : "memory");
                    unsigned target = (unsigned)(t + 1) * NCTA;
                    unsigned v;
                    do {
                        asm volatile("ld.acquire.gpu.u32 %0, [%1];"
                                     : "=r"(v) : "l"(&g_count) : "memory");
                    } while (v < target);
                    asm volatile("st.release.cta.shared.u32 [%0], %1;"
                                 :: "r"(flagaddr), "r"((unsigned)(t + 1))
                                 : "memory");
                }
                __syncwarp();
            }
        }
    }
}

extern "C" void kernel_launch(void* const* d_in, const int* in_sizes, int n_in,
                              void* d_out, int out_size) {
    const float* x   = (const float*)d_in[0];
    const float* wxi = (const float*)d_in[1];
    const float* wxf = (const float*)d_in[2];
    const float* wxc = (const float*)d_in[3];
    const float* whi = (const float*)d_in[4];
    const float* whf = (const float*)d_in[5];
    const float* whc = (const float*)d_in[6];
    const float* bi  = (const float*)d_in[7];
    const float* bf  = (const float*)d_in[8];
    const float* bc  = (const float*)d_in[9];
    const float* h0  = (const float*)d_in[10];
    const float* c0  = (const float*)d_in[11];
    float* out = (float*)d_out;

    proj_kernel<<<dim3(8, TT), 256>>>(x, wxi, wxf, wxc, bi, bf, bc);
    init_kernel<<<(BB * UU + 255) / 256, 256>>>(h0);

    bool launched = false;
    cudaError_t e1 = cudaFuncSetAttribute(
        lstm_cluster, cudaFuncAttributeNonPortableClusterSizeAllowed, 1);
    cudaError_t e2 = cudaFuncSetAttribute(
        lstm_cluster, cudaFuncAttributeMaxDynamicSharedMemorySize, CSM_TOTAL);
    if (e1 == cudaSuccess && e2 == cudaSuccess) {
        cudaLaunchConfig_t cfg = {};
        cfg.gridDim = dim3(NCTA, 1, 1);
        cfg.blockDim = dim3(256, 1, 1);
        cfg.dynamicSmemBytes = CSM_TOTAL;
        cudaLaunchAttribute at[1];
        at[0].id = cudaLaunchAttributeClusterDimension;
        at[0].val.clusterDim.x = CL;
        at[0].val.clusterDim.y = 1;
        at[0].val.clusterDim.z = 1;
        cfg.attrs = at;
        cfg.numAttrs = 1;
        cudaError_t e3 = cudaLaunchKernelEx(&cfg, lstm_cluster,
                                            whi, whf, whc, h0, c0, out);
        if (e3 == cudaSuccess) launched = true;
        else (void)cudaGetLastError();
    } else {
        (void)cudaGetLastError();
    }
    if (!launched) {
        cudaFuncSetAttribute(lstm_fallback,
                             cudaFuncAttributeMaxDynamicSharedMemorySize,
                             SM_TOTAL);
        lstm_fallback<<<NCTA, NTH, SM_TOTAL>>>(whi, whf, whc, c0, out);
    }
}

// round 15
// speedup vs baseline: 2.4264x; 2.3093x over previous
#include <cuda_runtime.h>
#include <cuda_fp16.h>
#include <cstdint>

#define BB 64
#define TT 512
#define DD 256
#define UU 512

// ---- lstm (tensor-core) config ----
#define NL 64             // lstm CTAs (each owns 8 u-cols x 3 gates)
#define NTHL 160          // 4 compute warps + 1 poller warp
#define HS_ROW 1040       // fp16 h row stride in smem bytes (512*2 + 16 pad)
#define HS_BYTES (64 * HS_ROW)             // 66560
#define WF_OFF   HS_BYTES
#define WF_BYTES (32 * 3 * 32 * 8)         // 24576 B-fragments
#define LFLAG_OFF (WF_OFF + WF_BYTES)      // 91136
#define LSM_TOTAL (LFLAG_OFF + 16)

// Scratch (static device arrays; no cudaMalloc anywhere).
__device__ float  g_xp[3][TT][BB][UU];     // input projections [g][t][b][u]
__device__ __half g_hbuf[2][BB * UU];      // ping-pong hidden state (fp16)
__device__ unsigned g_count;               // grid barrier counter

// ---- packed f32x2 helpers (proj kernel) ----
__device__ __forceinline__ void fma2(unsigned long long &d, unsigned long long a,
                                     unsigned long long b) {
    asm("fma.rn.f32x2 %0, %1, %2, %0;" : "+l"(d) : "l"(a), "l"(b));
}
__device__ __forceinline__ float2 upk(unsigned long long v) {
    float2 r;
    asm("mov.b64 {%0, %1}, %2;" : "=f"(r.x), "=f"(r.y) : "l"(v));
    return r;
}
__device__ __forceinline__ void cp16(uint32_t dst, const void* src) {
    asm volatile("cp.async.cg.shared.global [%0], [%1], 16;" :: "r"(dst), "l"(src));
}
__device__ __forceinline__ float fsig(float x) {
    return __fdividef(1.0f, 1.0f + __expf(-x));
}
__device__ __forceinline__ float ftanh(float x) {
    float e = __expf(-2.0f * fabsf(x));
    float r = __fdividef(1.0f - e, 1.0f + e);
    return copysignf(r, x);
}

// ============================================================================
// Phase 1: xp[g][t][b][u] = x[b,t,:] @ w_xg[:,u] + b_g[u]   (unchanged)
// ============================================================================
__global__ void __launch_bounds__(256, 2) proj_kernel(
    const float* __restrict__ x,
    const float* __restrict__ wxi, const float* __restrict__ wxf,
    const float* __restrict__ wxc,
    const float* __restrict__ bi, const float* __restrict__ bf,
    const float* __restrict__ bc) {
    __shared__ __align__(16) float xs[64][33];
    __shared__ __align__(16) float ws[3][32][64];

    const int tid = threadIdx.x;
    const int t = blockIdx.y;
    const int ub = blockIdx.x * 64;

    const int ug = tid & 15;
    const int bg = tid >> 4;
    const int ul = ug << 2;
    const int b0 = bg << 2;

    unsigned long long acc[3][4][2];
#pragma unroll
    for (int g = 0; g < 3; ++g)
#pragma unroll
        for (int i = 0; i < 4; ++i) { acc[g][i][0] = 0ull; acc[g][i][1] = 0ull; }

    for (int k0 = 0; k0 < DD; k0 += 32) {
#pragma unroll
        for (int i = 0; i < 8; ++i) {
            int idx = tid + i * 256;
            int bb = idx >> 5, kk = idx & 31;
            xs[bb][kk] = x[(bb * TT + t) * DD + k0 + kk];
        }
#pragma unroll
        for (int i = 0; i < 24; ++i) {
            int idx = tid + i * 256;
            int g = idx >> 11, r = idx & 2047, kk = r >> 6, uu = r & 63;
            const float* w = (g == 0) ? wxi : ((g == 1) ? wxf : wxc);
            ws[g][kk][uu] = w[(k0 + kk) * UU + ub + uu];
        }
        __syncthreads();
#pragma unroll
        for (int kk = 0; kk < 32; ++kk) {
            unsigned long long xb[4];
#pragma unroll
            for (int i = 0; i < 4; ++i) {
                unsigned xv = __float_as_uint(xs[b0 + i][kk]);
                asm("mov.b64 %0, {%1, %1};" : "=l"(xb[i]) : "r"(xv));
            }
#pragma unroll
            for (int g = 0; g < 3; ++g) {
                const ulonglong2 wv = *(const ulonglong2*)&ws[g][kk][ul];
#pragma unroll
                for (int i = 0; i < 4; ++i) {
                    fma2(acc[g][i][0], xb[i], wv.x);
                    fma2(acc[g][i][1], xb[i], wv.y);
                }
            }
        }
        __syncthreads();
    }

    const float* biases[3] = {bi, bf, bc};
#pragma unroll
    for (int g = 0; g < 3; ++g) {
        float2 bv0 = *(const float2*)&biases[g][ub + ul];
        float2 bv1 = *(const float2*)&biases[g][ub + ul + 2];
#pragma unroll
        for (int i = 0; i < 4; ++i) {
            float2 r0 = upk(acc[g][i][0]);
            float2 r1 = upk(acc[g][i][1]);
            r0.x += bv0.x; r0.y += bv0.y;
            r1.x += bv1.x; r1.y += bv1.y;
            float* dst = &g_xp[g][t][b0 + i][ub + ul];
            *(float2*)dst = r0;
            *(float2*)(dst + 2) = r1;
        }
    }
}

__global__ void init_kernel(const float* __restrict__ h0) {
    int i = blockIdx.x * blockDim.x + threadIdx.x;
    if (i < BB * UU) g_hbuf[1][i] = __float2half_rn(h0[i]);
    if (i == 0) g_count = 0u;
}

// ============================================================================
// Phase 2: tensor-core recurrent kernel. 64 CTAs x 160 threads.
// Warps 0..3 compute (warp w owns batch rows w*16..+15, all 8 u-cols x 3
// gates); warp 4 = grid-barrier poller (R10 design, 64 arrivals/step).
// GEMM: out[64 x 24] += h[64 x 512] @ W[512 x 24] via mma.m16n8k16 f16->f32.
// N-tiles = gates {i,f,c} -> all 3 pre-activations for one (b,u) land in the
// SAME lane: no reduction phase at all.
// h fp16 staged per-warp (own 16 rows) via cp.async into 1040B-padded rows
// (ldmatrix conflict-free); W packed once into B-fragment layout in smem.
// ============================================================================
__global__ void __launch_bounds__(NTHL, 1) lstm_mma(
    const float* __restrict__ whi, const float* __restrict__ whf,
    const float* __restrict__ whc, const float* __restrict__ c0,
    float* __restrict__ out) {
    extern __shared__ __align__(16) char sm[];
    uint2* wf = (uint2*)(sm + WF_OFF);

    const int tid = threadIdx.x;
    const int w = tid >> 5, lane = tid & 31;
    const int u0 = blockIdx.x * 8;

    // pack W into B-fragment layout: wf[(ks*3+nt)*32 + lane] = {b0, b1}
    // lane holds col n = lane>>2 (u-offset), k = ks*16 + 2*(lane&3) (+1,+8,+9)
    for (int i = tid; i < 32 * 3 * 32; i += NTHL) {
        int l = i & 31, nt = (i >> 5) % 3, ks = i / 96;
        const float* ws = (nt == 0) ? whi : ((nt == 1) ? whf : whc);
        const float* p = ws + u0 + (l >> 2);
        int k0 = ks * 16 + 2 * (l & 3);
        unsigned h0a = __half_as_ushort(__float2half_rn(p[(size_t)k0 * UU]));
        unsigned h1a = __half_as_ushort(__float2half_rn(p[(size_t)(k0 + 1) * UU]));
        unsigned h2a = __half_as_ushort(__float2half_rn(p[(size_t)(k0 + 8) * UU]));
        unsigned h3a = __half_as_ushort(__float2half_rn(p[(size_t)(k0 + 9) * UU]));
        uint2 v;
        v.x = (h1a << 16) | h0a;
        v.y = (h3a << 16) | h2a;
        wf[(ks * 3 + nt) * 32 + l] = v;
    }

    const uint32_t smbase = (uint32_t)__cvta_generic_to_shared(sm);
    const uint32_t flagaddr = smbase + LFLAG_OFF;
    if (tid == 0) *(unsigned*)(sm + LFLAG_OFF) = 0u;

    // per-lane compute geometry
    const int r0 = w * 16 + (lane >> 2);
    const int r1 = r0 + 8;
    const int uc0 = 2 * (lane & 3);
    // ldmatrix A address: lane -> (row, k-halfsel)
    const int lrow = w * 16 + (lane & 7) + ((lane >> 3) & 1) * 8;
    const uint32_t abase = smbase + (uint32_t)(lrow * HS_ROW + ((lane >> 4) * 16));

    // xp offsets for this lane's 4 outputs
    int bo[4];
    bo[0] = r0 * UU + u0 + uc0; bo[1] = bo[0] + 1;
    bo[2] = r1 * UU + u0 + uc0; bo[3] = bo[2] + 1;
    const float* xb = &g_xp[0][0][0][0];
    const size_t gstride = (size_t)TT * BB * UU;

    float cst[4];
    if (tid < 128) {
#pragma unroll
        for (int j = 0; j < 4; ++j) cst[j] = c0[bo[j]];
    }
    float* outp0 = out + (size_t)r0 * TT * UU + u0 + uc0;
    float* outp1 = out + (size_t)r1 * TT * UU + u0 + uc0;

    __syncthreads();

    for (int t = 0; t < TT; ++t) {
        if (tid < 128) {
            // prefetch xp(t) (12 scalars) before the flag wait
            float xpv[3][4];
#pragma unroll
            for (int g = 0; g < 3; ++g)
#pragma unroll
                for (int j = 0; j < 4; ++j)
                    xpv[g][j] = __ldcg(xb + (size_t)g * gstride +
                                       (size_t)t * (BB * UU) + bo[j]);

            if (t > 0) {
                unsigned v;
                do {
                    asm volatile("ld.acquire.cta.shared.u32 %0, [%1];"
                                 : "=r"(v) : "r"(flagaddr) : "memory");
                } while (v < (unsigned)t);
            }

            // stage this warp's 16 h rows (fp16): 32 chunks of 16B per lane
            const __half* hsrc = &g_hbuf[(t + 1) & 1][0];
#pragma unroll
            for (int it = 0; it < 32; ++it) {
                int idx = lane + it * 32;            // [0,1024)
                int r = w * 16 + (idx >> 6);
                int s = idx & 63;
                cp16(smbase + (uint32_t)(r * HS_ROW + s * 16),
                     hsrc + r * 512 + s * 8);
            }
            asm volatile("cp.async.commit_group;");
            asm volatile("cp.async.wait_group 0;");
            __syncwarp();

            // k-loop: 32 ksteps, 3 gate tiles, 2 accumulator banks per gate
            float c[3][2][4];
#pragma unroll
            for (int nt = 0; nt < 3; ++nt)
#pragma unroll
                for (int p = 0; p < 2; ++p)
#pragma unroll
                    for (int j = 0; j < 4; ++j) c[nt][p][j] = 0.0f;

#pragma unroll 8
            for (int ks = 0; ks < 32; ++ks) {
                uint32_t a0, a1, a2, a3;
                asm volatile(
                    "ldmatrix.sync.aligned.m8n8.x4.shared.b16 "
                    "{%0,%1,%2,%3}, [%4];"
                    : "=r"(a0), "=r"(a1), "=r"(a2), "=r"(a3)
                    : "r"(abase + (uint32_t)(ks * 32)));
                const int p = ks & 1;
#pragma unroll
                for (int nt = 0; nt < 3; ++nt) {
                    uint2 b = wf[(ks * 3 + nt) * 32 + lane];
                    asm volatile(
                        "mma.sync.aligned.m16n8k16.row.col.f32.f16.f16.f32 "
                        "{%0,%1,%2,%3},{%4,%5,%6,%7},{%8,%9},{%0,%1,%2,%3};"
                        : "+f"(c[nt][p][0]), "+f"(c[nt][p][1]),
                          "+f"(c[nt][p][2]), "+f"(c[nt][p][3])
                        : "r"(a0), "r"(a1), "r"(a2), "r"(a3),
                          "r"(b.x), "r"(b.y));
                }
            }

            // gates + state update, all in-register
            float hn[4];
#pragma unroll
            for (int j = 0; j < 4; ++j) {
                float si = xpv[0][j] + c[0][0][j] + c[0][1][j];
                float sf = xpv[1][j] + c[1][0][j] + c[1][1][j];
                float sc = xpv[2][j] + c[2][0][j] + c[2][1][j];
                float ig = fsig(si);
                float fg = fsig(sf);
                float ci = ftanh(sc);
                cst[j] = fg * cst[j] + ig * ci;
                hn[j] = ftanh(cst[j]);
            }

            // write h (fp16, ping-pong) and out (fp32)
            {
                __half2 p0 = __halves2half2(__float2half_rn(hn[0]),
                                            __float2half_rn(hn[1]));
                __half2 p1 = __halves2half2(__float2half_rn(hn[2]),
                                            __float2half_rn(hn[3]));
                __half* hb = &g_hbuf[t & 1][0];
                asm volatile("st.global.cg.b32 [%0], %1;"
                             :: "l"(hb + r0 * 512 + u0 + uc0),
                                "r"(*(unsigned*)&p0) : "memory");
                asm volatile("st.global.cg.b32 [%0], %1;"
                             :: "l"(hb + r1 * 512 + u0 + uc0),
                                "r"(*(unsigned*)&p1) : "memory");
                asm volatile("st.global.cg.v2.f32 [%0], {%1, %2};"
                             :: "l"(outp0 + (size_t)t * UU),
                                "f"(hn[0]), "f"(hn[1]) : "memory");
                asm volatile("st.global.cg.v2.f32 [%0], {%1, %2};"
                             :: "l"(outp1 + (size_t)t * UU),
                                "f"(hn[2]), "f"(hn[3]) : "memory");
            }

            if (t < TT - 1) {
                asm volatile("membar.cta;" ::: "memory");
                asm volatile("bar.arrive 1, %0;" :: "n"(NTHL) : "memory");
            }
        } else {
            // poller warp
            if (t < TT - 1) {
                asm volatile("bar.sync 1, %0;" :: "n"(NTHL) : "memory");
                if (lane == 0) {
                    asm volatile("red.release.gpu.global.add.u32 [%0], 1;"
                                 :: "l"(&g_count) : "memory");
                    unsigned target = (unsigned)(t + 1) * NL;
                    unsigned v;
                    do {
                        asm volatile("ld.acquire.gpu.u32 %0, [%1];"
                                     : "=r"(v) : "l"(&g_count) : "memory");
                    } while (v < target);
                    asm volatile("st.release.cta.shared.u32 [%0], %1;"
                                 :: "r"(flagaddr), "r"((unsigned)(t + 1))
                                 : "memory");
                }
                __syncwarp();
            }
        }
    }
}

extern "C" void kernel_launch(void* const* d_in, const int* in_sizes, int n_in,
                              void* d_out, int out_size) {
    const float* x   = (const float*)d_in[0];
    const float* wxi = (const float*)d_in[1];
    const float* wxf = (const float*)d_in[2];
    const float* wxc = (const float*)d_in[3];
    const float* whi = (const float*)d_in[4];
    const float* whf = (const float*)d_in[5];
    const float* whc = (const float*)d_in[6];
    const float* bi  = (const float*)d_in[7];
    const float* bf  = (const float*)d_in[8];
    const float* bc  = (const float*)d_in[9];
    const float* h0  = (const float*)d_in[10];
    const float* c0  = (const float*)d_in[11];
    float* out = (float*)d_out;

    cudaFuncSetAttribute(lstm_mma, cudaFuncAttributeMaxDynamicSharedMemorySize,
                         LSM_TOTAL);

    proj_kernel<<<dim3(8, TT), 256>>>(x, wxi, wxf, wxc, bi, bf, bc);
    init_kernel<<<(BB * UU + 255) / 256, 256>>>(h0);
    lstm_mma<<<NL, NTHL, LSM_TOTAL>>>(whi, whf, whc, c0, out);
}

// round 16
// speedup vs baseline: 2.9491x; 1.2154x over previous
#include <cuda_runtime.h>
#include <cuda_fp16.h>
#include <cstdint>

#define BB 64
#define TT 512
#define DD 256
#define UU 512

// ---- lstm (tensor-core) config ----
#define NL 64             // lstm CTAs (each owns 8 u-cols x 3 gates)
#define NTHL 160          // 4 compute warps + 1 poller warp
#define HS_ROW 1040       // fp16 h row stride in smem bytes
#define HS_BYTES (64 * HS_ROW)             // 66560
#define WF_OFF   HS_BYTES
#define WF_BYTES (32 * 3 * 32 * 8)         // 24576 B-fragments
#define LFLAG_OFF (WF_OFF + WF_BYTES)      // 91136
#define LSM_TOTAL (LFLAG_OFF + 16)

// ---- proj (tensor-core) config ----
#define PA_ROW 528                         // A tile row stride bytes (512+16)
#define PA_BYTES (128 * PA_ROW)            // 67584
#define PW_OFF   PA_BYTES
#define PW_ROW 144                         // W tile row stride bytes (128+16)
#define PW_BYTES (256 * PW_ROW)            // 36864
#define PSM_TOTAL (PW_OFF + PW_BYTES)      // 104448

// Scratch (static device arrays; no cudaMalloc anywhere).
__device__ float  g_xp[3][TT][BB][UU];     // input projections [g][t][b][u]
__device__ __half g_hbuf[2][BB * UU];      // ping-pong hidden state (fp16)
__device__ __half g_xh[BB * TT * DD];      // x in fp16, row m=b*T+t
__device__ __half g_wh[3][DD][UU];         // w_x in fp16
__device__ unsigned g_count;               // grid barrier counter

__device__ __forceinline__ void cp16(uint32_t dst, const void* src) {
    asm volatile("cp.async.cg.shared.global [%0], [%1], 16;" :: "r"(dst), "l"(src));
}
__device__ __forceinline__ float fsig(float x) {
    return __fdividef(1.0f, 1.0f + __expf(-x));
}
__device__ __forceinline__ float ftanh(float x) {
    float e = __expf(-2.0f * fabsf(x));
    float r = __fdividef(1.0f - e, 1.0f + e);
    return copysignf(r, x);
}

// ============================================================================
// Convert: x -> fp16, w_x -> fp16, h0 -> fp16 hbuf, reset g_count
// ============================================================================
__global__ void convert_kernel(const float* __restrict__ x,
                               const float* __restrict__ wxi,
                               const float* __restrict__ wxf,
                               const float* __restrict__ wxc,
                               const float* __restrict__ h0) {
    const int idx = blockIdx.x * blockDim.x + threadIdx.x;
    const int stride = gridDim.x * blockDim.x;
    // x: 8.4M floats as 4.19M float2 -> half2
    __half2* xd = (__half2*)g_xh;
    const float2* xs = (const float2*)x;
    for (int i = idx; i < BB * TT * DD / 2; i += stride)
        xd[i] = __float22half2_rn(xs[i]);
    // w: 3 x 131072 floats as pairs
    for (int i = idx; i < 3 * DD * UU / 2; i += stride) {
        int g = i / (DD * UU / 2), r = i % (DD * UU / 2);
        const float* ws = (g == 0) ? wxi : ((g == 1) ? wxf : wxc);
        float2 v = ((const float2*)ws)[r];
        ((__half2*)&g_wh[g][0][0])[r] = __float22half2_rn(v);
    }
    for (int i = idx; i < BB * UU; i += stride)
        g_hbuf[1][i] = __float2half_rn(h0[i]);
    if (idx == 0) g_count = 0u;
}

// ============================================================================
// Phase 1 (tensor cores): xp[g] = x @ w_xg + b_g.
// Grid (256, 8, 3): 128 M-rows x 64 u-cols x 1 gate per CTA; K=256 whole.
// 8 warps: warp (wm=w&3, wn=w>>2) -> m32 x n32; 16 k-steps of
// 2 A-ldmatrix.x4 + 2 B-ldmatrix.x4.trans + 8 mma.m16n8k16.
// ============================================================================
__global__ void __launch_bounds__(256) proj_mma(
    const float* __restrict__ bi, const float* __restrict__ bf,
    const float* __restrict__ bc) {
    extern __shared__ __align__(16) char sm[];
    const int tid = threadIdx.x;
    const int w = tid >> 5, lane = tid & 31;
    const int bm = blockIdx.x, ub = blockIdx.y * 64, g = blockIdx.z;
    const uint32_t smbase = (uint32_t)__cvta_generic_to_shared(sm);

    // stage A: 128 rows x 512B
    {
        const __half* asrc = g_xh + (size_t)(bm * 128) * DD;
        for (int i = tid; i < 4096; i += 256) {
            int r = i >> 5, s = i & 31;
            cp16(smbase + (uint32_t)(r * PA_ROW + s * 16), asrc + r * DD + s * 8);
        }
        const __half* wsrc = &g_wh[g][0][0] + ub;
        for (int i = tid; i < 2048; i += 256) {
            int k = i >> 3, s = i & 7;
            cp16(smbase + (uint32_t)(PW_OFF + k * PW_ROW + s * 16),
                 wsrc + k * UU + s * 8);
        }
    }
    asm volatile("cp.async.commit_group;");
    asm volatile("cp.async.wait_group 0;");
    __syncthreads();

    const int wm = w & 3, wn = w >> 2;
    const uint32_t abase = smbase +
        (uint32_t)((wm * 32 + (lane & 15)) * PA_ROW + (lane >> 4) * 16);
    const uint32_t bbase = smbase + (uint32_t)(PW_OFF + (lane & 15) * PW_ROW +
        (wn * 32 + (lane >> 4) * 8) * 2);

    float acc[2][4][4];
#pragma unroll
    for (int mt = 0; mt < 2; ++mt)
#pragma unroll
        for (int nt = 0; nt < 4; ++nt)
#pragma unroll
            for (int j = 0; j < 4; ++j) acc[mt][nt][j] = 0.0f;

#pragma unroll
    for (int ks = 0; ks < 16; ++ks) {
        uint32_t A[2][4], Bf[2][4];
#pragma unroll
        for (int mt = 0; mt < 2; ++mt)
            asm volatile(
                "ldmatrix.sync.aligned.m8n8.x4.shared.b16 {%0,%1,%2,%3}, [%4];"
                : "=r"(A[mt][0]), "=r"(A[mt][1]), "=r"(A[mt][2]), "=r"(A[mt][3])
                : "r"(abase + (uint32_t)(mt * 16 * PA_ROW + ks * 32)));
#pragma unroll
        for (int bt = 0; bt < 2; ++bt)
            asm volatile(
                "ldmatrix.sync.aligned.m8n8.x4.trans.shared.b16 "
                "{%0,%1,%2,%3}, [%4];"
                : "=r"(Bf[bt][0]), "=r"(Bf[bt][1]), "=r"(Bf[bt][2]), "=r"(Bf[bt][3])
                : "r"(bbase + (uint32_t)(bt * 32 + ks * 16 * PW_ROW)));
#pragma unroll
        for (int mt = 0; mt < 2; ++mt)
#pragma unroll
            for (int nt = 0; nt < 4; ++nt) {
                const int bt = nt >> 1, o = (nt & 1) * 2;
                asm volatile(
                    "mma.sync.aligned.m16n8k16.row.col.f32.f16.f16.f32 "
                    "{%0,%1,%2,%3},{%4,%5,%6,%7},{%8,%9},{%0,%1,%2,%3};"
                    : "+f"(acc[mt][nt][0]), "+f"(acc[mt][nt][1]),
                      "+f"(acc[mt][nt][2]), "+f"(acc[mt][nt][3])
                    : "r"(A[mt][0]), "r"(A[mt][1]), "r"(A[mt][2]), "r"(A[mt][3]),
                      "r"(Bf[bt][o]), "r"(Bf[bt][o + 1]));
            }
    }

    const float* bp = (g == 0) ? bi : ((g == 1) ? bf : bc);
#pragma unroll
    for (int mt = 0; mt < 2; ++mt) {
        int m = bm * 128 + wm * 32 + mt * 16 + (lane >> 2);
        int b = m >> 9, t = m & 511;
#pragma unroll
        for (int nt = 0; nt < 4; ++nt) {
            int u = ub + wn * 32 + nt * 8 + 2 * (lane & 3);
            float2 bv = *(const float2*)(bp + u);
            float* d0 = &g_xp[g][t][b][u];
            float* d1 = &g_xp[g][t + 8][b][u];
            d0[0] = acc[mt][nt][0] + bv.x;
            d0[1] = acc[mt][nt][1] + bv.y;
            d1[0] = acc[mt][nt][2] + bv.x;
            d1[1] = acc[mt][nt][3] + bv.y;
        }
    }
}

// ============================================================================
// Phase 2: tensor-core recurrent kernel (R15, unchanged). 64 CTAs x 160 thr.
// ============================================================================
__global__ void __launch_bounds__(NTHL, 1) lstm_mma(
    const float* __restrict__ whi, const float* __restrict__ whf,
    const float* __restrict__ whc, const float* __restrict__ c0,
    float* __restrict__ out) {
    extern __shared__ __align__(16) char sm[];
    uint2* wf = (uint2*)(sm + WF_OFF);

    const int tid = threadIdx.x;
    const int w = tid >> 5, lane = tid & 31;
    const int u0 = blockIdx.x * 8;

    for (int i = tid; i < 32 * 3 * 32; i += NTHL) {
        int l = i & 31, nt = (i >> 5) % 3, ks = i / 96;
        const float* ws = (nt == 0) ? whi : ((nt == 1) ? whf : whc);
        const float* p = ws + u0 + (l >> 2);
        int k0 = ks * 16 + 2 * (l & 3);
        unsigned h0a = __half_as_ushort(__float2half_rn(p[(size_t)k0 * UU]));
        unsigned h1a = __half_as_ushort(__float2half_rn(p[(size_t)(k0 + 1) * UU]));
        unsigned h2a = __half_as_ushort(__float2half_rn(p[(size_t)(k0 + 8) * UU]));
        unsigned h3a = __half_as_ushort(__float2half_rn(p[(size_t)(k0 + 9) * UU]));
        uint2 v;
        v.x = (h1a << 16) | h0a;
        v.y = (h3a << 16) | h2a;
        wf[(ks * 3 + nt) * 32 + l] = v;
    }

    const uint32_t smbase = (uint32_t)__cvta_generic_to_shared(sm);
    const uint32_t flagaddr = smbase + LFLAG_OFF;
    if (tid == 0) *(unsigned*)(sm + LFLAG_OFF) = 0u;

    const int r0 = w * 16 + (lane >> 2);
    const int r1 = r0 + 8;
    const int uc0 = 2 * (lane & 3);
    const int lrow = w * 16 + (lane & 7) + ((lane >> 3) & 1) * 8;
    const uint32_t abase = smbase + (uint32_t)(lrow * HS_ROW + ((lane >> 4) * 16));

    int bo[4];
    bo[0] = r0 * UU + u0 + uc0; bo[1] = bo[0] + 1;
    bo[2] = r1 * UU + u0 + uc0; bo[3] = bo[2] + 1;
    const float* xb = &g_xp[0][0][0][0];
    const size_t gstride = (size_t)TT * BB * UU;

    float cst[4];
    if (tid < 128) {
#pragma unroll
        for (int j = 0; j < 4; ++j) cst[j] = c0[bo[j]];
    }
    float* outp0 = out + (size_t)r0 * TT * UU + u0 + uc0;
    float* outp1 = out + (size_t)r1 * TT * UU + u0 + uc0;

    __syncthreads();

    for (int t = 0; t < TT; ++t) {
        if (tid < 128) {
            float xpv[3][4];
#pragma unroll
            for (int g = 0; g < 3; ++g)
#pragma unroll
                for (int j = 0; j < 4; ++j)
                    xpv[g][j] = __ldcg(xb + (size_t)g * gstride +
                                       (size_t)t * (BB * UU) + bo[j]);

            if (t > 0) {
                unsigned v;
                do {
                    asm volatile("ld.acquire.cta.shared.u32 %0, [%1];"
                                 : "=r"(v) : "r"(flagaddr) : "memory");
                } while (v < (unsigned)t);
            }

            const __half* hsrc = &g_hbuf[(t + 1) & 1][0];
#pragma unroll
            for (int it = 0; it < 32; ++it) {
                int idx = lane + it * 32;
                int r = w * 16 + (idx >> 6);
                int s = idx & 63;
                cp16(smbase + (uint32_t)(r * HS_ROW + s * 16),
                     hsrc + r * 512 + s * 8);
            }
            asm volatile("cp.async.commit_group;");
            asm volatile("cp.async.wait_group 0;");
            __syncwarp();

            float c[3][2][4];
#pragma unroll
            for (int nt = 0; nt < 3; ++nt)
#pragma unroll
                for (int p = 0; p < 2; ++p)
#pragma unroll
                    for (int j = 0; j < 4; ++j) c[nt][p][j] = 0.0f;

#pragma unroll 8
            for (int ks = 0; ks < 32; ++ks) {
                uint32_t a0, a1, a2, a3;
                asm volatile(
                    "ldmatrix.sync.aligned.m8n8.x4.shared.b16 "
                    "{%0,%1,%2,%3}, [%4];"
                    : "=r"(a0), "=r"(a1), "=r"(a2), "=r"(a3)
                    : "r"(abase + (uint32_t)(ks * 32)));
                const int p = ks & 1;
#pragma unroll
                for (int nt = 0; nt < 3; ++nt) {
                    uint2 b = wf[(ks * 3 + nt) * 32 + lane];
                    asm volatile(
                        "mma.sync.aligned.m16n8k16.row.col.f32.f16.f16.f32 "
                        "{%0,%1,%2,%3},{%4,%5,%6,%7},{%8,%9},{%0,%1,%2,%3};"
                        : "+f"(c[nt][p][0]), "+f"(c[nt][p][1]),
                          "+f"(c[nt][p][2]), "+f"(c[nt][p][3])
                        : "r"(a0), "r"(a1), "r"(a2), "r"(a3),
                          "r"(b.x), "r"(b.y));
                }
            }

            float hn[4];
#pragma unroll
            for (int j = 0; j < 4; ++j) {
                float si = xpv[0][j] + c[0][0][j] + c[0][1][j];
                float sf = xpv[1][j] + c[1][0][j] + c[1][1][j];
                float sc = xpv[2][j] + c[2][0][j] + c[2][1][j];
                float ig = fsig(si);
                float fg = fsig(sf);
                float ci = ftanh(sc);
                cst[j] = fg * cst[j] + ig * ci;
                hn[j] = ftanh(cst[j]);
            }

            {
                __half2 p0 = __halves2half2(__float2half_rn(hn[0]),
                                            __float2half_rn(hn[1]));
                __half2 p1 = __halves2half2(__float2half_rn(hn[2]),
                                            __float2half_rn(hn[3]));
                __half* hb = &g_hbuf[t & 1][0];
                asm volatile("st.global.cg.b32 [%0], %1;"
                             :: "l"(hb + r0 * 512 + u0 + uc0),
                                "r"(*(unsigned*)&p0) : "memory");
                asm volatile("st.global.cg.b32 [%0], %1;"
                             :: "l"(hb + r1 * 512 + u0 + uc0),
                                "r"(*(unsigned*)&p1) : "memory");
                asm volatile("st.global.cg.v2.f32 [%0], {%1, %2};"
                             :: "l"(outp0 + (size_t)t * UU),
                                "f"(hn[0]), "f"(hn[1]) : "memory");
                asm volatile("st.global.cg.v2.f32 [%0], {%1, %2};"
                             :: "l"(outp1 + (size_t)t * UU),
                                "f"(hn[2]), "f"(hn[3]) : "memory");
            }

            if (t < TT - 1) {
                asm volatile("membar.cta;" ::: "memory");
                asm volatile("bar.arrive 1, %0;" :: "n"(NTHL) : "memory");
            }
        } else {
            if (t < TT - 1) {
                asm volatile("bar.sync 1, %0;" :: "n"(NTHL) : "memory");
                if (lane == 0) {
                    asm volatile("red.release.gpu.global.add.u32 [%0], 1;"
                                 :: "l"(&g_count) : "memory");
                    unsigned target = (unsigned)(t + 1) * NL;
                    unsigned v;
                    do {
                        asm volatile("ld.acquire.gpu.u32 %0, [%1];"
                                     : "=r"(v) : "l"(&g_count) : "memory");
                    } while (v < target);
                    asm volatile("st.release.cta.shared.u32 [%0], %1;"
                                 :: "r"(flagaddr), "r"((unsigned)(t + 1))
                                 : "memory");
                }
                __syncwarp();
            }
        }
    }
}

extern "C" void kernel_launch(void* const* d_in, const int* in_sizes, int n_in,
                              void* d_out, int out_size) {
    const float* x   = (const float*)d_in[0];
    const float* wxi = (const float*)d_in[1];
    const float* wxf = (const float*)d_in[2];
    const float* wxc = (const float*)d_in[3];
    const float* whi = (const float*)d_in[4];
    const float* whf = (const float*)d_in[5];
    const float* whc = (const float*)d_in[6];
    const float* bi  = (const float*)d_in[7];
    const float* bf  = (const float*)d_in[8];
    const float* bc  = (const float*)d_in[9];
    const float* h0  = (const float*)d_in[10];
    const float* c0  = (const float*)d_in[11];
    float* out = (float*)d_out;

    cudaFuncSetAttribute(proj_mma, cudaFuncAttributeMaxDynamicSharedMemorySize,
                         PSM_TOTAL);
    cudaFuncSetAttribute(lstm_mma, cudaFuncAttributeMaxDynamicSharedMemorySize,
                         LSM_TOTAL);

    convert_kernel<<<2048, 512>>>(x, wxi, wxf, wxc, h0);
    proj_mma<<<dim3(256, 8, 3), 256, PSM_TOTAL>>>(bi, bf, bc);
    lstm_mma<<<NL, NTHL, LSM_TOTAL>>>(whi, whf, whc, c0, out);
}

// round 17
// speedup vs baseline: 3.1528x; 1.0691x over previous
#include <cuda_runtime.h>
#include <cuda_fp16.h>
#include <cstdint>

#define BB 64
#define TT 512
#define DD 256
#define UU 512

// ---- lstm (tensor-core) config ----
#define NL 64             // lstm CTAs (each owns 8 u-cols x 3 gates)
#define NTHL 160          // 4 compute warps + 1 poller warp
#define HS_ROW 1040       // fp16 h row stride in smem bytes
#define HS_BYTES (64 * HS_ROW)             // 66560
#define WF_OFF   HS_BYTES
#define WF_BYTES (32 * 3 * 32 * 8)         // 24576 B-fragments
#define LFLAG_OFF (WF_OFF + WF_BYTES)      // 91136
#define LSM_TOTAL (LFLAG_OFF + 16)

// ---- proj (tensor-core) config ----
#define PA_ROW 528                         // A tile row stride bytes (512+16)
#define PA_BYTES (128 * PA_ROW)            // 67584
#define PW_OFF   PA_BYTES
#define PW_ROW 144                         // W tile row stride bytes (128+16)
#define PW_BYTES (256 * PW_ROW)            // 36864
#define PSM_TOTAL (PW_OFF + PW_BYTES)      // 104448

// Scratch (static device arrays; no cudaMalloc anywhere).
__device__ float  g_xp[3][TT][BB][UU];     // input projections [g][t][b][u]
__device__ __half g_hbuf[2][BB * UU];      // ping-pong hidden state (fp16)
__device__ __half g_xh[BB * TT * DD];      // x in fp16, row m=b*T+t
__device__ __half g_wh[3][DD][UU];         // w_x in fp16
__device__ unsigned g_count;               // grid barrier counter

__device__ __forceinline__ void cp16(uint32_t dst, const void* src) {
    asm volatile("cp.async.cg.shared.global [%0], [%1], 16;" :: "r"(dst), "l"(src));
}
__device__ __forceinline__ float fsig(float x) {
    return __fdividef(1.0f, 1.0f + __expf(-x));
}
__device__ __forceinline__ float ftanh(float x) {
    float e = __expf(-2.0f * fabsf(x));
    float r = __fdividef(1.0f - e, 1.0f + e);
    return copysignf(r, x);
}

// ============================================================================
// Convert: x -> fp16, w_x -> fp16, h0 -> fp16 hbuf, reset g_count
// ============================================================================
__global__ void convert_kernel(const float* __restrict__ x,
                               const float* __restrict__ wxi,
                               const float* __restrict__ wxf,
                               const float* __restrict__ wxc,
                               const float* __restrict__ h0) {
    const int idx = blockIdx.x * blockDim.x + threadIdx.x;
    const int stride = gridDim.x * blockDim.x;
    __half2* xd = (__half2*)g_xh;
    const float2* xs = (const float2*)x;
    for (int i = idx; i < BB * TT * DD / 2; i += stride)
        xd[i] = __float22half2_rn(xs[i]);
    for (int i = idx; i < 3 * DD * UU / 2; i += stride) {
        int g = i / (DD * UU / 2), r = i % (DD * UU / 2);
        const float* ws = (g == 0) ? wxi : ((g == 1) ? wxf : wxc);
        float2 v = ((const float2*)ws)[r];
        ((__half2*)&g_wh[g][0][0])[r] = __float22half2_rn(v);
    }
    for (int i = idx; i < BB * UU; i += stride)
        g_hbuf[1][i] = __float2half_rn(h0[i]);
    if (idx == 0) g_count = 0u;
}

// ============================================================================
// Phase 1 (tensor cores): xp[g] = x @ w_xg + b_g.  (R16, unchanged)
// ============================================================================
__global__ void __launch_bounds__(256) proj_mma(
    const float* __restrict__ bi, const float* __restrict__ bf,
    const float* __restrict__ bc) {
    extern __shared__ __align__(16) char sm[];
    const int tid = threadIdx.x;
    const int w = tid >> 5, lane = tid & 31;
    const int bm = blockIdx.x, ub = blockIdx.y * 64, g = blockIdx.z;
    const uint32_t smbase = (uint32_t)__cvta_generic_to_shared(sm);

    {
        const __half* asrc = g_xh + (size_t)(bm * 128) * DD;
        for (int i = tid; i < 4096; i += 256) {
            int r = i >> 5, s = i & 31;
            cp16(smbase + (uint32_t)(r * PA_ROW + s * 16), asrc + r * DD + s * 8);
        }
        const __half* wsrc = &g_wh[g][0][0] + ub;
        for (int i = tid; i < 2048; i += 256) {
            int k = i >> 3, s = i & 7;
            cp16(smbase + (uint32_t)(PW_OFF + k * PW_ROW + s * 16),
                 wsrc + k * UU + s * 8);
        }
    }
    asm volatile("cp.async.commit_group;");
    asm volatile("cp.async.wait_group 0;");
    __syncthreads();

    const int wm = w & 3, wn = w >> 2;
    const uint32_t abase = smbase +
        (uint32_t)((wm * 32 + (lane & 15)) * PA_ROW + (lane >> 4) * 16);
    const uint32_t bbase = smbase + (uint32_t)(PW_OFF + (lane & 15) * PW_ROW +
        (wn * 32 + (lane >> 4) * 8) * 2);

    float acc[2][4][4];
#pragma unroll
    for (int mt = 0; mt < 2; ++mt)
#pragma unroll
        for (int nt = 0; nt < 4; ++nt)
#pragma unroll
            for (int j = 0; j < 4; ++j) acc[mt][nt][j] = 0.0f;

#pragma unroll
    for (int ks = 0; ks < 16; ++ks) {
        uint32_t A[2][4], Bf[2][4];
#pragma unroll
        for (int mt = 0; mt < 2; ++mt)
            asm volatile(
                "ldmatrix.sync.aligned.m8n8.x4.shared.b16 {%0,%1,%2,%3}, [%4];"
                : "=r"(A[mt][0]), "=r"(A[mt][1]), "=r"(A[mt][2]), "=r"(A[mt][3])
                : "r"(abase + (uint32_t)(mt * 16 * PA_ROW + ks * 32)));
#pragma unroll
        for (int bt = 0; bt < 2; ++bt)
            asm volatile(
                "ldmatrix.sync.aligned.m8n8.x4.trans.shared.b16 "
                "{%0,%1,%2,%3}, [%4];"
                : "=r"(Bf[bt][0]), "=r"(Bf[bt][1]), "=r"(Bf[bt][2]), "=r"(Bf[bt][3])
                : "r"(bbase + (uint32_t)(bt * 32 + ks * 16 * PW_ROW)));
#pragma unroll
        for (int mt = 0; mt < 2; ++mt)
#pragma unroll
            for (int nt = 0; nt < 4; ++nt) {
                const int bt = nt >> 1, o = (nt & 1) * 2;
                asm volatile(
                    "mma.sync.aligned.m16n8k16.row.col.f32.f16.f16.f32 "
                    "{%0,%1,%2,%3},{%4,%5,%6,%7},{%8,%9},{%0,%1,%2,%3};"
                    : "+f"(acc[mt][nt][0]), "+f"(acc[mt][nt][1]),
                      "+f"(acc[mt][nt][2]), "+f"(acc[mt][nt][3])
                    : "r"(A[mt][0]), "r"(A[mt][1]), "r"(A[mt][2]), "r"(A[mt][3]),
                      "r"(Bf[bt][o]), "r"(Bf[bt][o + 1]));
            }
    }

    const float* bp = (g == 0) ? bi : ((g == 1) ? bf : bc);
#pragma unroll
    for (int mt = 0; mt < 2; ++mt) {
        int m = bm * 128 + wm * 32 + mt * 16 + (lane >> 2);
        int b = m >> 9, t = m & 511;
#pragma unroll
        for (int nt = 0; nt < 4; ++nt) {
            int u = ub + wn * 32 + nt * 8 + 2 * (lane & 3);
            float2 bv = *(const float2*)(bp + u);
            float* d0 = &g_xp[g][t][b][u];
            float* d1 = &g_xp[g][t + 8][b][u];
            d0[0] = acc[mt][nt][0] + bv.x;
            d0[1] = acc[mt][nt][1] + bv.y;
            d1[0] = acc[mt][nt][2] + bv.x;
            d1[1] = acc[mt][nt][3] + bv.y;
        }
    }
}

// ============================================================================
// Phase 2: tensor-core recurrent kernel. 64 CTAs x 160 threads.
// R16 core + (a) two-half pipelined h staging (slots 0-31 / 32-63, separate
// commit groups; compute ks 0-15 under the second half's transfer), and
// (b) fp32 out-stores moved AFTER the barrier arrive (off the critical path).
// ============================================================================
__global__ void __launch_bounds__(NTHL, 1) lstm_mma(
    const float* __restrict__ whi, const float* __restrict__ whf,
    const float* __restrict__ whc, const float* __restrict__ c0,
    float* __restrict__ out) {
    extern __shared__ __align__(16) char sm[];
    uint2* wf = (uint2*)(sm + WF_OFF);

    const int tid = threadIdx.x;
    const int w = tid >> 5, lane = tid & 31;
    const int u0 = blockIdx.x * 8;

    for (int i = tid; i < 32 * 3 * 32; i += NTHL) {
        int l = i & 31, nt = (i >> 5) % 3, ks = i / 96;
        const float* ws = (nt == 0) ? whi : ((nt == 1) ? whf : whc);
        const float* p = ws + u0 + (l >> 2);
        int k0 = ks * 16 + 2 * (l & 3);
        unsigned h0a = __half_as_ushort(__float2half_rn(p[(size_t)k0 * UU]));
        unsigned h1a = __half_as_ushort(__float2half_rn(p[(size_t)(k0 + 1) * UU]));
        unsigned h2a = __half_as_ushort(__float2half_rn(p[(size_t)(k0 + 8) * UU]));
        unsigned h3a = __half_as_ushort(__float2half_rn(p[(size_t)(k0 + 9) * UU]));
        uint2 v;
        v.x = (h1a << 16) | h0a;
        v.y = (h3a << 16) | h2a;
        wf[(ks * 3 + nt) * 32 + l] = v;
    }

    const uint32_t smbase = (uint32_t)__cvta_generic_to_shared(sm);
    const uint32_t flagaddr = smbase + LFLAG_OFF;
    if (tid == 0) *(unsigned*)(sm + LFLAG_OFF) = 0u;

    const int r0 = w * 16 + (lane >> 2);
    const int r1 = r0 + 8;
    const int uc0 = 2 * (lane & 3);
    const int lrow = w * 16 + (lane & 7) + ((lane >> 3) & 1) * 8;
    const uint32_t abase = smbase + (uint32_t)(lrow * HS_ROW + ((lane >> 4) * 16));

    int bo[4];
    bo[0] = r0 * UU + u0 + uc0; bo[1] = bo[0] + 1;
    bo[2] = r1 * UU + u0 + uc0; bo[3] = bo[2] + 1;
    const float* xb = &g_xp[0][0][0][0];
    const size_t gstride = (size_t)TT * BB * UU;

    float cst[4];
    if (tid < 128) {
#pragma unroll
        for (int j = 0; j < 4; ++j) cst[j] = c0[bo[j]];
    }
    float* outp0 = out + (size_t)r0 * TT * UU + u0 + uc0;
    float* outp1 = out + (size_t)r1 * TT * UU + u0 + uc0;

    __syncthreads();

    for (int t = 0; t < TT; ++t) {
        if (tid < 128) {
            float xpv[3][4];
#pragma unroll
            for (int g = 0; g < 3; ++g)
#pragma unroll
                for (int j = 0; j < 4; ++j)
                    xpv[g][j] = __ldcg(xb + (size_t)g * gstride +
                                       (size_t)t * (BB * UU) + bo[j]);

            if (t > 0) {
                unsigned v;
                do {
                    asm volatile("ld.acquire.cta.shared.u32 %0, [%1];"
                                 : "=r"(v) : "r"(flagaddr) : "memory");
                } while (v < (unsigned)t);
            }

            // stage this warp's 16 h rows in two k-halves (pipelined)
            const __half* hsrc = &g_hbuf[(t + 1) & 1][0];
#pragma unroll
            for (int half = 0; half < 2; ++half) {
#pragma unroll
                for (int it = 0; it < 16; ++it) {
                    int idx = lane + it * 32;        // [0,512)
                    int r = w * 16 + (idx >> 5);
                    int s = half * 32 + (idx & 31);
                    cp16(smbase + (uint32_t)(r * HS_ROW + s * 16),
                         hsrc + r * 512 + s * 8);
                }
                asm volatile("cp.async.commit_group;");
            }

            float c[3][2][4];
#pragma unroll
            for (int nt = 0; nt < 3; ++nt)
#pragma unroll
                for (int p = 0; p < 2; ++p)
#pragma unroll
                    for (int j = 0; j < 4; ++j) c[nt][p][j] = 0.0f;

            // first k-half: only slots 0..31 needed
            asm volatile("cp.async.wait_group 1;");
            __syncwarp();
#pragma unroll 8
            for (int ks = 0; ks < 16; ++ks) {
                uint32_t a0, a1, a2, a3;
                asm volatile(
                    "ldmatrix.sync.aligned.m8n8.x4.shared.b16 "
                    "{%0,%1,%2,%3}, [%4];"
                    : "=r"(a0), "=r"(a1), "=r"(a2), "=r"(a3)
                    : "r"(abase + (uint32_t)(ks * 32)));
                const int p = ks & 1;
#pragma unroll
                for (int nt = 0; nt < 3; ++nt) {
                    uint2 b = wf[(ks * 3 + nt) * 32 + lane];
                    asm volatile(
                        "mma.sync.aligned.m16n8k16.row.col.f32.f16.f16.f32 "
                        "{%0,%1,%2,%3},{%4,%5,%6,%7},{%8,%9},{%0,%1,%2,%3};"
                        : "+f"(c[nt][p][0]), "+f"(c[nt][p][1]),
                          "+f"(c[nt][p][2]), "+f"(c[nt][p][3])
                        : "r"(a0), "r"(a1), "r"(a2), "r"(a3),
                          "r"(b.x), "r"(b.y));
                }
            }
            // second k-half
            asm volatile("cp.async.wait_group 0;");
            __syncwarp();
#pragma unroll 8
            for (int ks = 16; ks < 32; ++ks) {
                uint32_t a0, a1, a2, a3;
                asm volatile(
                    "ldmatrix.sync.aligned.m8n8.x4.shared.b16 "
                    "{%0,%1,%2,%3}, [%4];"
                    : "=r"(a0), "=r"(a1), "=r"(a2), "=r"(a3)
                    : "r"(abase + (uint32_t)(ks * 32)));
                const int p = ks & 1;
#pragma unroll
                for (int nt = 0; nt < 3; ++nt) {
                    uint2 b = wf[(ks * 3 + nt) * 32 + lane];
                    asm volatile(
                        "mma.sync.aligned.m16n8k16.row.col.f32.f16.f16.f32 "
                        "{%0,%1,%2,%3},{%4,%5,%6,%7},{%8,%9},{%0,%1,%2,%3};"
                        : "+f"(c[nt][p][0]), "+f"(c[nt][p][1]),
                          "+f"(c[nt][p][2]), "+f"(c[nt][p][3])
                        : "r"(a0), "r"(a1), "r"(a2), "r"(a3),
                          "r"(b.x), "r"(b.y));
                }
            }

            float hn[4];
#pragma unroll
            for (int j = 0; j < 4; ++j) {
                float si = xpv[0][j] + c[0][0][j] + c[0][1][j];
                float sf = xpv[1][j] + c[1][0][j] + c[1][1][j];
                float sc = xpv[2][j] + c[2][0][j] + c[2][1][j];
                float ig = fsig(si);
                float fg = fsig(sf);
                float ci = ftanh(sc);
                cst[j] = fg * cst[j] + ig * ci;
                hn[j] = ftanh(cst[j]);
            }

            // h stores (critical path), then arrive, then out stores
            {
                __half2 p0 = __halves2half2(__float2half_rn(hn[0]),
                                            __float2half_rn(hn[1]));
                __half2 p1 = __halves2half2(__float2half_rn(hn[2]),
                                            __float2half_rn(hn[3]));
                __half* hb = &g_hbuf[t & 1][0];
                asm volatile("st.global.cg.b32 [%0], %1;"
                             :: "l"(hb + r0 * 512 + u0 + uc0),
                                "r"(*(unsigned*)&p0) : "memory");
                asm volatile("st.global.cg.b32 [%0], %1;"
                             :: "l"(hb + r1 * 512 + u0 + uc0),
                                "r"(*(unsigned*)&p1) : "memory");
            }
            if (t < TT - 1) {
                asm volatile("membar.cta;" ::: "memory");
                asm volatile("bar.arrive 1, %0;" :: "n"(NTHL) : "memory");
            }
            asm volatile("st.global.cg.v2.f32 [%0], {%1, %2};"
                         :: "l"(outp0 + (size_t)t * UU),
                            "f"(hn[0]), "f"(hn[1]) : "memory");
            asm volatile("st.global.cg.v2.f32 [%0], {%1, %2};"
                         :: "l"(outp1 + (size_t)t * UU),
                            "f"(hn[2]), "f"(hn[3]) : "memory");
        } else {
            if (t < TT - 1) {
                asm volatile("bar.sync 1, %0;" :: "n"(NTHL) : "memory");
                if (lane == 0) {
                    asm volatile("red.release.gpu.global.add.u32 [%0], 1;"
                                 :: "l"(&g_count) : "memory");
                    unsigned target = (unsigned)(t + 1) * NL;
                    unsigned v;
                    do {
                        asm volatile("ld.acquire.gpu.u32 %0, [%1];"
                                     : "=r"(v) : "l"(&g_count) : "memory");
                    } while (v < target);
                    asm volatile("st.release.cta.shared.u32 [%0], %1;"
                                 :: "r"(flagaddr), "r"((unsigned)(t + 1))
                                 : "memory");
                }
                __syncwarp();
            }
        }
    }
}

extern "C" void kernel_launch(void* const* d_in, const int* in_sizes, int n_in,
                              void* d_out, int out_size) {
    const float* x   = (const float*)d_in[0];
    const float* wxi = (const float*)d_in[1];
    const float* wxf = (const float*)d_in[2];
    const float* wxc = (const float*)d_in[3];
    const float* whi = (const float*)d_in[4];
    const float* whf = (const float*)d_in[5];
    const float* whc = (const float*)d_in[6];
    const float* bi  = (const float*)d_in[7];
    const float* bf  = (const float*)d_in[8];
    const float* bc  = (const float*)d_in[9];
    const float* h0  = (const float*)d_in[10];
    const float* c0  = (const float*)d_in[11];
    float* out = (float*)d_out;

    cudaFuncSetAttribute(proj_mma, cudaFuncAttributeMaxDynamicSharedMemorySize,
                         PSM_TOTAL);
    cudaFuncSetAttribute(lstm_mma, cudaFuncAttributeMaxDynamicSharedMemorySize,
                         LSM_TOTAL);

    convert_kernel<<<2048, 512>>>(x, wxi, wxf, wxc, h0);
    proj_mma<<<dim3(256, 8, 3), 256, PSM_TOTAL>>>(bi, bf, bc);
    lstm_mma<<<NL, NTHL, LSM_TOTAL>>>(whi, whf, whc, c0, out);
}